// round 3
// baseline (speedup 1.0000x reference)
#include <cuda_runtime.h>
#include <cstdint>
#include <cstddef>

// ---------------------------------------------------------------------------
// sMGU cell: B=65536, IN=256, H=512
// tf32 mma.sync GEMM [B,768]@[768,1024] (gates f/c interleaved per column
// pair) + fused epilogue. R2: pre-rounded A in global scratch, ldmatrix
// fragment loads, 5-stage cp.async pipeline with one barrier per chunk.
// ---------------------------------------------------------------------------

#define H_DIM   512
#define BH      33554432ull            // B*H
#define KTOT    768
#define KC      16                     // k-chunk (floats)
#define NCHUNK  48                     // 768/16
#define NSTAGE  5
#define ROWF    20                     // smem row stride (pad 16 -> 20 floats)
#define STG_W   (2 * 128 * ROWF)       // words per stage (A tile + B tile)
#define SMEM_BYTES (NSTAGE * STG_W * 4)  // 102400 B

// Pre-rounded operands (tf32 RN). g_A rows = batch, cols = [x | h_prev].
// g_Wt[n][k]: h = n>>1, gate = n&1 (0=f, 1=c).
__device__ float g_A [65536ull * KTOT];
__device__ float g_Wt[1024 * KTOT];

// ------------------------------- helpers -----------------------------------
__device__ __forceinline__ uint32_t smem_u32(const void* p) {
    uint32_t a;
    asm("{ .reg .u64 t; cvta.to.shared.u64 t, %1; cvt.u32.u64 %0, t; }"
        : "=r"(a) : "l"(p));
    return a;
}
__device__ __forceinline__ void cp16(uint32_t dst, const void* src) {
    asm volatile("cp.async.cg.shared.global [%0], [%1], 16;"
                 :: "r"(dst), "l"(src));
}
__device__ __forceinline__ float tf32rn(float v) {
    asm("cvt.rna.tf32.f32 %0, %0;" : "+f"(v));
    return v;
}
__device__ __forceinline__ void ldm_x4(uint32_t* r, uint32_t addr) {
    asm volatile("ldmatrix.sync.aligned.m8n8.x4.shared.b16 {%0,%1,%2,%3}, [%4];"
                 : "=r"(r[0]), "=r"(r[1]), "=r"(r[2]), "=r"(r[3]) : "r"(addr));
}
__device__ __forceinline__ void ldm_x2(uint32_t* r, uint32_t addr) {
    asm volatile("ldmatrix.sync.aligned.m8n8.x2.shared.b16 {%0,%1}, [%2];"
                 : "=r"(r[0]), "=r"(r[1]) : "r"(addr));
}
__device__ __forceinline__ void mma_tf32(float* d, const uint32_t* a,
                                         const uint32_t* b) {
    asm volatile(
        "mma.sync.aligned.m16n8k8.row.col.f32.tf32.tf32.f32 "
        "{%0,%1,%2,%3}, {%4,%5,%6,%7}, {%8,%9}, {%0,%1,%2,%3};"
        : "+f"(d[0]), "+f"(d[1]), "+f"(d[2]), "+f"(d[3])
        : "r"(a[0]), "r"(a[1]), "r"(a[2]), "r"(a[3]), "r"(b[0]), "r"(b[1]));
}

__device__ __forceinline__ float tanh_fast(float v) {
    float e = __expf(2.0f * v);
    return 1.0f - __fdividef(2.0f, e + 1.0f);
}
__device__ __forceinline__ void cell(float df, float dc, float bfe, float bce,
                                     float mpv, float cpv, float npv,
                                     float& h, float& c, float& n, float& m) {
    float a  = df + bfe + mpv;              // log f_t + m_prev
    m = fmaxf(a, 0.0f);
    float e  = __expf(-fabsf(a));           // one exp covers both branches
    float fp = (a >= 0.0f) ? 1.0f : e;      // exp(a - m)
    float ip = (a >= 0.0f) ? e : 1.0f;      // exp(-m)
    float th = tanh_fast(dc + bce);
    c = fp * cpv + ip * th;
    n = fp * npv + ip;
    h = tanh_fast(__fdividef(c, fmaxf(n, 1e-8f)));
}

// ------------------------------ prep kernels -------------------------------
__global__ void prep_weights(const float* __restrict__ wf,
                             const float* __restrict__ wc,
                             const float* __restrict__ rf,
                             const float* __restrict__ rc) {
    int n = blockIdx.x;                 // 0..1023
    int h = n >> 1, gate = n & 1;
    const float* W = gate ? wc : wf;
    const float* R = gate ? rc : rf;
    for (int k = threadIdx.x; k < KTOT; k += blockDim.x) {
        float v = (k < 256) ? W[(size_t)k * H_DIM + h]
                            : R[(size_t)(k - 256) * H_DIM + h];
        g_Wt[(size_t)n * KTOT + k] = tf32rn(v);
    }
}

// g_A[row][0:256]=tf32rn(x[row]); g_A[row][256:768]=tf32rn(h_prev[row])
__global__ void prep_act(const float4* __restrict__ x4,
                         const float4* __restrict__ h4) {
    size_t idx = (size_t)blockIdx.x * blockDim.x + threadIdx.x;  // float4 id
    int row = (int)(idx / 192);
    int c4  = (int)(idx % 192);
    float4 v = (c4 < 64) ? x4[(size_t)row * 64 + c4]
                         : h4[(size_t)row * 128 + (c4 - 64)];
    v.x = tf32rn(v.x); v.y = tf32rn(v.y); v.z = tf32rn(v.z); v.w = tf32rn(v.w);
    reinterpret_cast<float4*>(g_A)[idx] = v;
}

// ------------------------------ main kernel --------------------------------
// CTA 128 rows x 128 cols. 8 warps, (wm 0..1) x (wn 0..3), warp tile 64x32.
extern "C" __global__ void __launch_bounds__(256, 2)
smgu_main(const float* __restrict__ cprev, const float* __restrict__ nprev,
          const float* __restrict__ mprev, const float* __restrict__ bfv,
          const float* __restrict__ bcv,   float* __restrict__ out) {
    extern __shared__ float smem[];
    const int tid  = threadIdx.x;
    const int lane = tid & 31, wid = tid >> 5;
    const int wm   = wid & 1,  wn  = wid >> 1;
    const int mtile = (int)blockIdx.x >> 3;
    const int ntile = (int)blockIdx.x & 7;
    const int m0  = mtile * 128;
    const int ncb = ntile * 128;

    const uint32_t sbase = smem_u32(smem);
    const float* __restrict__ asrc0 = g_A  + (size_t)m0  * KTOT;
    const float* __restrict__ bsrc0 = g_Wt + (size_t)ncb * KTOT;

    float acc[4][4][4];
#pragma unroll
    for (int i = 0; i < 4; i++)
#pragma unroll
        for (int j = 0; j < 4; j++)
#pragma unroll
            for (int r = 0; r < 4; r++) acc[i][j][r] = 0.0f;

    // loader: chunk c -> stage s (A 128x16 + B 128x16, 2 cp16 each/thread)
    auto load = [&](int c, int s) {
        const uint32_t abase = sbase + (uint32_t)(s * STG_W) * 4u;
        const uint32_t bbase = abase + (uint32_t)(128 * ROWF) * 4u;
        const float* ap = asrc0 + c * KC;
        const float* bp = bsrc0 + c * KC;
#pragma unroll
        for (int u = 0; u < 2; u++) {
            int i = tid + u * 256;
            int row = i >> 2, seg = i & 3;
            uint32_t doff = (uint32_t)(row * (ROWF * 4) + seg * 16);
            cp16(abase + doff, ap + (size_t)row * KTOT + seg * 4);
            cp16(bbase + doff, bp + (size_t)row * KTOT + seg * 4);
        }
        asm volatile("cp.async.commit_group;" ::: "memory");
    };

    load(0, 0); load(1, 1); load(2, 2); load(3, 3);

    // per-thread ldmatrix base offsets (within a stage)
    const uint32_t a_off = (uint32_t)(((wm * 64 + (lane & 15)) * ROWF
                                       + ((lane >> 4) << 2)) * 4);
    const uint32_t b_off = (uint32_t)((128 * ROWF
                                       + (wn * 32 + (lane & 7)) * ROWF
                                       + ((lane >> 3) & 1) * 4) * 4);

    int s = 0;
    for (int c = 0; c < NCHUNK; c++) {
        asm volatile("cp.async.wait_group 3;" ::: "memory");
        __syncthreads();

        // refill: chunk c+4 overwrites stage of chunk c-1 (safe post-barrier)
        if (c + 4 < NCHUNK) {
            int s4 = s + 4; if (s4 >= NSTAGE) s4 -= NSTAGE;
            load(c + 4, s4);
        } else {
            asm volatile("cp.async.commit_group;" ::: "memory");  // keep count
        }

        const uint32_t stg = sbase + (uint32_t)(s * STG_W) * 4u;
        const uint32_t ab  = stg + a_off;
        const uint32_t bb  = stg + b_off;
#pragma unroll
        for (int kk8 = 0; kk8 < 2; kk8++) {
            const uint32_t kb = (uint32_t)(kk8 * 8 * 4);
            uint32_t afr[4][4], bfr[4][2];
#pragma unroll
            for (int mf = 0; mf < 4; mf++)
                ldm_x4(afr[mf], ab + (uint32_t)(mf * 16 * ROWF * 4) + kb);
#pragma unroll
            for (int nf = 0; nf < 4; nf++)
                ldm_x2(bfr[nf], bb + (uint32_t)(nf * 8 * ROWF * 4) + kb);
#pragma unroll
            for (int mf = 0; mf < 4; mf++)
#pragma unroll
                for (int nf = 0; nf < 4; nf++)
                    mma_tf32(acc[mf][nf], afr[mf], bfr[nf]);
        }
        if (++s == NSTAGE) s = 0;
    }

    // ------------------------------ epilogue -----------------------------
    // frag: c0=(row, col_f), c1=(row, col_c); c2/c3 at row+8.
    float* out_h = out;
    float* out_c = out + BH;
    float* out_n = out + 2 * BH;
    float* out_m = out + 3 * BH;

#pragma unroll
    for (int nf = 0; nf < 4; nf++) {
        const int col = ncb + wn * 32 + nf * 8 + 2 * (lane & 3);  // even col
        const int hg  = col >> 1;
        const float bfe = bfv[hg];
        const float bce = bcv[hg];
#pragma unroll
        for (int mf = 0; mf < 4; mf++) {
            const int rbase = m0 + wm * 64 + mf * 16 + (lane >> 2);
#pragma unroll
            for (int hf = 0; hf < 2; hf++) {
                const size_t idx = (size_t)(rbase + hf * 8) * H_DIM + hg;
                float rh, rc, rn, rm;
                cell(acc[mf][nf][hf * 2], acc[mf][nf][hf * 2 + 1],
                     bfe, bce, mprev[idx], cprev[idx], nprev[idx],
                     rh, rc, rn, rm);
                out_h[idx] = rh;
                out_c[idx] = rc;
                out_n[idx] = rn;
                out_m[idx] = rm;
            }
        }
    }
}

// ------------------------------ launcher -----------------------------------
extern "C" void kernel_launch(void* const* d_in, const int* in_sizes, int n_in,
                              void* d_out, int out_size) {
    const float* x     = (const float*)d_in[0];
    const float* hprev = (const float*)d_in[1];
    const float* cprev = (const float*)d_in[2];
    const float* nprev = (const float*)d_in[3];
    const float* mprev = (const float*)d_in[4];
    const float* wf    = (const float*)d_in[5];
    const float* wc    = (const float*)d_in[6];
    const float* rf    = (const float*)d_in[7];
    const float* rc    = (const float*)d_in[8];
    const float* bf    = (const float*)d_in[9];
    const float* bc    = (const float*)d_in[10];

    cudaFuncSetAttribute(smgu_main,
                         cudaFuncAttributeMaxDynamicSharedMemorySize,
                         SMEM_BYTES);

    prep_weights<<<1024, 256>>>(wf, wc, rf, rc);
    prep_act<<<49152, 256>>>((const float4*)x, (const float4*)hprev);
    smgu_main<<<4096, 256, SMEM_BYTES>>>(cprev, nprev, mprev,
                                         bf, bc, (float*)d_out);
}

// round 5
// speedup vs baseline: 1.3997x; 1.3997x over previous
#include <cuda_runtime.h>
#include <cstdint>
#include <cstddef>

// ---------------------------------------------------------------------------
// sMGU cell: B=65536, IN=256, H=512
// tf32 mma.sync GEMM [B,768]@[768,1024] (f/c gates interleaved per column
// pair) + fused epilogue. R4 = R3 with the epilogue reader indexing fixed
// (each 128-float SMEM row is consumed by 16 lanes, 2 rows per warp-iter;
// R3 let all 32 lanes read one row -> SMEM + global OOB -> crash).
// ---------------------------------------------------------------------------

#define H_DIM   512
#define BH      33554432ull            // B*H
#define KTOT    768
#define KC      32                     // k-chunk (floats)
#define NCHUNK  24                     // 768/32
#define NSTAGE  3
#define ROWF    36                     // smem row stride (pad 32 -> 36 floats)
#define STG_W   (2 * 128 * ROWF)       // words per stage (A tile + B tile)
#define SMEM_BYTES (NSTAGE * STG_W * 4)  // 110592 B -> 2 CTAs/SM
#define EPI_STRIDE 132                 // epilogue smem row stride (floats)

// Pre-rounded weights (tf32 RN). g_Wt[n][k]: h = n>>1, gate = n&1 (0=f, 1=c).
__device__ float g_Wt[1024 * KTOT];

// ------------------------------- helpers -----------------------------------
__device__ __forceinline__ uint32_t smem_u32(const void* p) {
    uint32_t a;
    asm("{ .reg .u64 t; cvta.to.shared.u64 t, %1; cvt.u32.u64 %0, t; }"
        : "=r"(a) : "l"(p));
    return a;
}
__device__ __forceinline__ void cp16(uint32_t dst, const void* src) {
    asm volatile("cp.async.cg.shared.global [%0], [%1], 16;"
                 :: "r"(dst), "l"(src));
}
__device__ __forceinline__ float tf32rn(float v) {
    asm("cvt.rna.tf32.f32 %0, %0;" : "+f"(v));
    return v;
}
__device__ __forceinline__ void ldm_x4(uint32_t* r, uint32_t addr) {
    asm volatile("ldmatrix.sync.aligned.m8n8.x4.shared.b16 {%0,%1,%2,%3}, [%4];"
                 : "=r"(r[0]), "=r"(r[1]), "=r"(r[2]), "=r"(r[3]) : "r"(addr));
}
__device__ __forceinline__ void ldm_x2(uint32_t* r, uint32_t addr) {
    asm volatile("ldmatrix.sync.aligned.m8n8.x2.shared.b16 {%0,%1}, [%2];"
                 : "=r"(r[0]), "=r"(r[1]) : "r"(addr));
}
__device__ __forceinline__ void mma_tf32(float* d, const uint32_t* a,
                                         const uint32_t* b) {
    asm volatile(
        "mma.sync.aligned.m16n8k8.row.col.f32.tf32.tf32.f32 "
        "{%0,%1,%2,%3}, {%4,%5,%6,%7}, {%8,%9}, {%0,%1,%2,%3};"
        : "+f"(d[0]), "+f"(d[1]), "+f"(d[2]), "+f"(d[3])
        : "r"(a[0]), "r"(a[1]), "r"(a[2]), "r"(a[3]), "r"(b[0]), "r"(b[1]));
}

__device__ __forceinline__ float tanh_fast(float v) {
    float e = __expf(2.0f * v);
    return 1.0f - __fdividef(2.0f, e + 1.0f);
}
__device__ __forceinline__ void cell(float df, float dc, float bfe, float bce,
                                     float mpv, float cpv, float npv,
                                     float& h, float& c, float& n, float& m) {
    float a  = df + bfe + mpv;              // log f_t + m_prev
    m = fmaxf(a, 0.0f);
    float e  = __expf(-fabsf(a));           // one exp covers both branches
    float fp = (a >= 0.0f) ? 1.0f : e;      // exp(a - m)
    float ip = (a >= 0.0f) ? e : 1.0f;      // exp(-m)
    float th = tanh_fast(dc + bce);
    c = fp * cpv + ip * th;
    n = fp * npv + ip;
    h = tanh_fast(__fdividef(c, fmaxf(n, 1e-8f)));
}

// ------------------------------ prep kernel --------------------------------
__global__ void prep_weights(const float* __restrict__ wf,
                             const float* __restrict__ wc,
                             const float* __restrict__ rf,
                             const float* __restrict__ rc) {
    int n = blockIdx.x;                 // 0..1023
    int h = n >> 1, gate = n & 1;
    const float* W = gate ? wc : wf;
    const float* R = gate ? rc : rf;
    for (int k = threadIdx.x; k < KTOT; k += blockDim.x) {
        float v = (k < 256) ? W[(size_t)k * H_DIM + h]
                            : R[(size_t)(k - 256) * H_DIM + h];
        g_Wt[(size_t)n * KTOT + k] = tf32rn(v);
    }
}

// ------------------------------ main kernel --------------------------------
// CTA 128 rows x 128 cols. 8 warps, (wm 0..1) x (wn 0..3), warp tile 64x32.
extern "C" __global__ void __launch_bounds__(256, 2)
smgu_main(const float* __restrict__ x,     const float* __restrict__ hprev,
          const float* __restrict__ cprev, const float* __restrict__ nprev,
          const float* __restrict__ mprev, const float* __restrict__ bfv,
          const float* __restrict__ bcv,   float* __restrict__ out) {
    extern __shared__ float smem[];
    const int tid  = threadIdx.x;
    const int lane = tid & 31, wid = tid >> 5;
    const int wm   = wid & 1,  wn  = wid >> 1;
    const int mtile = (int)blockIdx.x >> 3;
    const int ntile = (int)blockIdx.x & 7;
    const int m0  = mtile * 128;
    const int ncb = ntile * 128;

    const uint32_t sbase = smem_u32(smem);

    float acc[4][4][4];
#pragma unroll
    for (int i = 0; i < 4; i++)
#pragma unroll
        for (int j = 0; j < 4; j++)
#pragma unroll
            for (int r = 0; r < 4; r++) acc[i][j][r] = 0.0f;

    // loader: chunk c -> stage s. A 128x32 + B 128x32, 4+4 cp16 per thread.
    auto load = [&](int c, int s) {
        const uint32_t abase = sbase + (uint32_t)(s * STG_W) * 4u;
        const uint32_t bbase = abase + (uint32_t)(128 * ROWF) * 4u;
        const float* asrc; int astr;
        if (c < 8) { asrc = x + c * KC;            astr = 256; }
        else       { asrc = hprev + (c - 8) * KC;  astr = 512; }
#pragma unroll
        for (int u = 0; u < 4; u++) {              // A: 128 rows x 8 segs
            int i = tid + u * 256;
            int row = i >> 3, seg = i & 7;
            cp16(abase + (uint32_t)(row * (ROWF * 4) + seg * 16),
                 asrc + (size_t)(m0 + row) * astr + seg * 4);
        }
        const float* bsrc = g_Wt + (size_t)ncb * KTOT + c * KC;
#pragma unroll
        for (int u = 0; u < 4; u++) {              // B: 128 rows x 8 segs
            int i = tid + u * 256;
            int row = i >> 3, seg = i & 7;
            cp16(bbase + (uint32_t)(row * (ROWF * 4) + seg * 16),
                 bsrc + (size_t)row * KTOT + seg * 4);
        }
        asm volatile("cp.async.commit_group;" ::: "memory");
    };

    load(0, 0);
    load(1, 1);

    // per-thread ldmatrix base offsets (bytes, within a stage)
    const uint32_t a_off = (uint32_t)(((wm * 64 + (lane & 15)) * ROWF
                                       + ((lane >> 4) << 2)) * 4);
    const uint32_t b_off = (uint32_t)((128 * ROWF
                                       + (wn * 32 + (lane & 7)) * ROWF
                                       + ((lane >> 3) & 1) * 4) * 4);

    for (int c = 0; c < NCHUNK; c++) {
        const int s = c % NSTAGE;
        asm volatile("cp.async.wait_group 1;" ::: "memory");
        __syncthreads();   // all warps have chunk c; all done reading c-1

        if (c + 2 < NCHUNK) load(c + 2, (c + 2) % NSTAGE);  // stage of c-1
        else asm volatile("cp.async.commit_group;" ::: "memory");

        const uint32_t stg = sbase + (uint32_t)(s * STG_W) * 4u;
        const uint32_t ab  = stg + a_off;
        const uint32_t bb  = stg + b_off;
#pragma unroll
        for (int kk8 = 0; kk8 < 4; kk8++) {
            const uint32_t kb = (uint32_t)(kk8 * 8 * 4);
            uint32_t afr[4][4], bfr[4][2];
#pragma unroll
            for (int mf = 0; mf < 4; mf++) {
                ldm_x4(afr[mf], ab + (uint32_t)(mf * 16 * ROWF * 4) + kb);
#pragma unroll
                for (int q = 0; q < 4; q++) {
                    float t = __uint_as_float(afr[mf][q]);
                    afr[mf][q] = __float_as_uint(tf32rn(t));
                }
            }
#pragma unroll
            for (int nf = 0; nf < 4; nf++)
                ldm_x2(bfr[nf], bb + (uint32_t)(nf * 8 * ROWF * 4) + kb);
#pragma unroll
            for (int mf = 0; mf < 4; mf++)
#pragma unroll
                for (int nf = 0; nf < 4; nf++)
                    mma_tf32(acc[mf][nf], afr[mf], bfr[nf]);
        }
    }

    // ------------------- epilogue: stage through SMEM ---------------------
    // epi tile: 128 rows x 128 floats (64 h-units), stride EPI_STRIDE.
    __syncthreads();                    // all mma reads of smem done

#pragma unroll
    for (int nf = 0; nf < 4; nf++) {
        const int col = wn * 32 + nf * 8 + 2 * (lane & 3);
#pragma unroll
        for (int mf = 0; mf < 4; mf++) {
            const int row = wm * 64 + mf * 16 + (lane >> 2);
            // (pre_f, pre_c) pairs as 8B stores
            *reinterpret_cast<float2*>(smem + row * EPI_STRIDE + col) =
                make_float2(acc[mf][nf][0], acc[mf][nf][1]);
            *reinterpret_cast<float2*>(smem + (row + 8) * EPI_STRIDE + col) =
                make_float2(acc[mf][nf][2], acc[mf][nf][3]);
        }
    }
    __syncthreads();

    float* out_h = out;
    float* out_c = out + BH;
    float* out_n = out + 2 * BH;
    float* out_m = out + 3 * BH;

    // reader: each row (128 floats = 64 h) consumed by 16 lanes; warp does
    // 2 rows per iteration -> 8 warps x 2 x 8 iters = 128 rows.
    const int ln = lane & 15;
    const int rsub = lane >> 4;
    const int hb = ntile * 64 + 4 * ln;           // global h of this 4-vector
    const float4 bf = *reinterpret_cast<const float4*>(bfv + hb);
    const float4 bc = *reinterpret_cast<const float4*>(bcv + hb);

#pragma unroll
    for (int u = 0; u < 8; u++) {
        const int r = wid * 2 + rsub + 16 * u;    // local row
        const float* sp = smem + r * EPI_STRIDE + 8 * ln;
        float4 q0 = *reinterpret_cast<const float4*>(sp);      // pf0 pc0 pf1 pc1
        float4 q1 = *reinterpret_cast<const float4*>(sp + 4);  // pf2 pc2 pf3 pc3

        const size_t g = (size_t)(m0 + r) * H_DIM + hb;
        float4 mp = *reinterpret_cast<const float4*>(mprev + g);
        float4 cp = *reinterpret_cast<const float4*>(cprev + g);
        float4 np = *reinterpret_cast<const float4*>(nprev + g);

        float4 rh, rc, rn, rm;
        cell(q0.x, q0.y, bf.x, bc.x, mp.x, cp.x, np.x, rh.x, rc.x, rn.x, rm.x);
        cell(q0.z, q0.w, bf.y, bc.y, mp.y, cp.y, np.y, rh.y, rc.y, rn.y, rm.y);
        cell(q1.x, q1.y, bf.z, bc.z, mp.z, cp.z, np.z, rh.z, rc.z, rn.z, rm.z);
        cell(q1.z, q1.w, bf.w, bc.w, mp.w, cp.w, np.w, rh.w, rc.w, rn.w, rm.w);

        *reinterpret_cast<float4*>(out_h + g) = rh;
        *reinterpret_cast<float4*>(out_c + g) = rc;
        *reinterpret_cast<float4*>(out_n + g) = rn;
        *reinterpret_cast<float4*>(out_m + g) = rm;
    }
}

// ------------------------------ launcher -----------------------------------
extern "C" void kernel_launch(void* const* d_in, const int* in_sizes, int n_in,
                              void* d_out, int out_size) {
    const float* x     = (const float*)d_in[0];
    const float* hprev = (const float*)d_in[1];
    const float* cprev = (const float*)d_in[2];
    const float* nprev = (const float*)d_in[3];
    const float* mprev = (const float*)d_in[4];
    const float* wf    = (const float*)d_in[5];
    const float* wc    = (const float*)d_in[6];
    const float* rf    = (const float*)d_in[7];
    const float* rc    = (const float*)d_in[8];
    const float* bf    = (const float*)d_in[9];
    const float* bc    = (const float*)d_in[10];

    cudaFuncSetAttribute(smgu_main,
                         cudaFuncAttributeMaxDynamicSharedMemorySize,
                         SMEM_BYTES);

    prep_weights<<<1024, 256>>>(wf, wc, rf, rc);
    smgu_main<<<4096, 256, SMEM_BYTES>>>(x, hprev, cprev, nprev, mprev,
                                         bf, bc, (float*)d_out);
}

// round 6
// speedup vs baseline: 1.4334x; 1.0241x over previous
#include <cuda_runtime.h>
#include <cstdint>
#include <cstddef>

// ---------------------------------------------------------------------------
// sMGU cell: B=65536, IN=256, H=512
// tf32 mma.sync GEMM [B,768]@[768,1024] (f/c gates interleaved per column
// pair) + fused epilogue. R5: warp tile 64x64 (4 warps/CTA, 128 threads) to
// halve SMEM-crossbar bytes per MAC — R4 was co-bound by LDS+STS (L1=48%)
// against the tensor pipe (49%).
// ---------------------------------------------------------------------------

#define H_DIM   512
#define BH      33554432ull            // B*H
#define KTOT    768
#define KC      32                     // k-chunk (floats)
#define NCHUNK  24                     // 768/32
#define NSTAGE  3
#define ROWF    36                     // smem row stride (pad 32 -> 36 floats)
#define STG_W   (2 * 128 * ROWF)       // words per stage (A tile + B tile)
#define SMEM_BYTES (NSTAGE * STG_W * 4)  // 110592 B -> 2 CTAs/SM
#define EPI_STRIDE 132                 // epilogue smem row stride (floats)

// Pre-rounded weights (tf32 RN). g_Wt[n][k]: h = n>>1, gate = n&1 (0=f, 1=c).
__device__ float g_Wt[1024 * KTOT];

// ------------------------------- helpers -----------------------------------
__device__ __forceinline__ uint32_t smem_u32(const void* p) {
    uint32_t a;
    asm("{ .reg .u64 t; cvta.to.shared.u64 t, %1; cvt.u32.u64 %0, t; }"
        : "=r"(a) : "l"(p));
    return a;
}
__device__ __forceinline__ void cp16(uint32_t dst, const void* src) {
    asm volatile("cp.async.cg.shared.global [%0], [%1], 16;"
                 :: "r"(dst), "l"(src));
}
__device__ __forceinline__ float tf32rn(float v) {
    asm("cvt.rna.tf32.f32 %0, %0;" : "+f"(v));
    return v;
}
__device__ __forceinline__ void ldm_x4(uint32_t* r, uint32_t addr) {
    asm volatile("ldmatrix.sync.aligned.m8n8.x4.shared.b16 {%0,%1,%2,%3}, [%4];"
                 : "=r"(r[0]), "=r"(r[1]), "=r"(r[2]), "=r"(r[3]) : "r"(addr));
}
__device__ __forceinline__ void mma_tf32(float* d, const uint32_t* a,
                                         const uint32_t* b) {
    asm volatile(
        "mma.sync.aligned.m16n8k8.row.col.f32.tf32.tf32.f32 "
        "{%0,%1,%2,%3}, {%4,%5,%6,%7}, {%8,%9}, {%0,%1,%2,%3};"
        : "+f"(d[0]), "+f"(d[1]), "+f"(d[2]), "+f"(d[3])
        : "r"(a[0]), "r"(a[1]), "r"(a[2]), "r"(a[3]), "r"(b[0]), "r"(b[1]));
}

__device__ __forceinline__ float tanh_fast(float v) {
    float e = __expf(2.0f * v);
    return 1.0f - __fdividef(2.0f, e + 1.0f);
}
__device__ __forceinline__ void cell(float df, float dc, float bfe, float bce,
                                     float mpv, float cpv, float npv,
                                     float& h, float& c, float& n, float& m) {
    float a  = df + bfe + mpv;              // log f_t + m_prev
    m = fmaxf(a, 0.0f);
    float e  = __expf(-fabsf(a));           // one exp covers both branches
    float fp = (a >= 0.0f) ? 1.0f : e;      // exp(a - m)
    float ip = (a >= 0.0f) ? e : 1.0f;      // exp(-m)
    float th = tanh_fast(dc + bce);
    c = fp * cpv + ip * th;
    n = fp * npv + ip;
    h = tanh_fast(__fdividef(c, fmaxf(n, 1e-8f)));
}

// ------------------------------ prep kernel --------------------------------
__global__ void prep_weights(const float* __restrict__ wf,
                             const float* __restrict__ wc,
                             const float* __restrict__ rf,
                             const float* __restrict__ rc) {
    int n = blockIdx.x;                 // 0..1023
    int h = n >> 1, gate = n & 1;
    const float* W = gate ? wc : wf;
    const float* R = gate ? rc : rf;
    for (int k = threadIdx.x; k < KTOT; k += blockDim.x) {
        float v = (k < 256) ? W[(size_t)k * H_DIM + h]
                            : R[(size_t)(k - 256) * H_DIM + h];
        g_Wt[(size_t)n * KTOT + k] = tf32rn(v);
    }
}

// ------------------------------ main kernel --------------------------------
// CTA 128 rows x 128 cols. 4 warps, (wm 0..1) x (wn 0..1), warp tile 64x64.
extern "C" __global__ void __launch_bounds__(128, 2)
smgu_main(const float* __restrict__ x,     const float* __restrict__ hprev,
          const float* __restrict__ cprev, const float* __restrict__ nprev,
          const float* __restrict__ mprev, const float* __restrict__ bfv,
          const float* __restrict__ bcv,   float* __restrict__ out) {
    extern __shared__ float smem[];
    const int tid  = threadIdx.x;
    const int lane = tid & 31, wid = tid >> 5;
    const int wm   = wid & 1,  wn  = wid >> 1;
    const int mtile = (int)blockIdx.x >> 3;
    const int ntile = (int)blockIdx.x & 7;
    const int m0  = mtile * 128;
    const int ncb = ntile * 128;

    const uint32_t sbase = smem_u32(smem);

    float acc[4][8][4];                  // mf x nf x frag = 128 regs
#pragma unroll
    for (int i = 0; i < 4; i++)
#pragma unroll
        for (int j = 0; j < 8; j++)
#pragma unroll
            for (int r = 0; r < 4; r++) acc[i][j][r] = 0.0f;

    // loader: chunk c -> stage s. A 128x32 + B 128x32, 8+8 cp16 per thread.
    auto load = [&](int c, int s) {
        const uint32_t abase = sbase + (uint32_t)(s * STG_W) * 4u;
        const uint32_t bbase = abase + (uint32_t)(128 * ROWF) * 4u;
        const float* asrc; int astr;
        if (c < 8) { asrc = x + c * KC;            astr = 256; }
        else       { asrc = hprev + (c - 8) * KC;  astr = 512; }
#pragma unroll
        for (int u = 0; u < 8; u++) {              // A: 128 rows x 8 segs
            int i = tid + u * 128;
            int row = i >> 3, seg = i & 7;
            cp16(abase + (uint32_t)(row * (ROWF * 4) + seg * 16),
                 asrc + (size_t)(m0 + row) * astr + seg * 4);
        }
        const float* bsrc = g_Wt + (size_t)ncb * KTOT + c * KC;
#pragma unroll
        for (int u = 0; u < 8; u++) {              // B: 128 rows x 8 segs
            int i = tid + u * 128;
            int row = i >> 3, seg = i & 7;
            cp16(bbase + (uint32_t)(row * (ROWF * 4) + seg * 16),
                 bsrc + (size_t)row * KTOT + seg * 4);
        }
        asm volatile("cp.async.commit_group;" ::: "memory");
    };

    load(0, 0);
    load(1, 1);

    // per-thread ldmatrix base offsets (bytes, within a stage)
    // A x4: lanes 0-15 -> rows 0-15 @k0, lanes 16-31 -> rows 0-15 @k4
    const uint32_t a_off = (uint32_t)(((wm * 64 + (lane & 15)) * ROWF
                                       + ((lane >> 4) << 2)) * 4);
    // B x4: group g=lane>>3; row = (g>>1)*8 + (lane&7); k-off = (g&1)*4
    const uint32_t b_off = (uint32_t)((128 * ROWF
                                       + (wn * 64 + ((lane >> 4) << 3)
                                          + (lane & 7)) * ROWF
                                       + (((lane >> 3) & 1) << 2)) * 4);

    for (int c = 0; c < NCHUNK; c++) {
        const int s = c % NSTAGE;
        asm volatile("cp.async.wait_group 1;" ::: "memory");
        __syncthreads();   // all warps have chunk c; all done reading c-1

        if (c + 2 < NCHUNK) load(c + 2, (c + 2) % NSTAGE);  // stage of c-1
        else asm volatile("cp.async.commit_group;" ::: "memory");

        const uint32_t stg = sbase + (uint32_t)(s * STG_W) * 4u;
        const uint32_t ab  = stg + a_off;
        const uint32_t bb  = stg + b_off;
#pragma unroll
        for (int kk8 = 0; kk8 < 4; kk8++) {
            const uint32_t kb = (uint32_t)(kk8 * 8 * 4);
            uint32_t afr[4][4], bfr[8][2];
#pragma unroll
            for (int mf = 0; mf < 4; mf++) {
                ldm_x4(afr[mf], ab + (uint32_t)(mf * 16 * ROWF * 4) + kb);
#pragma unroll
                for (int q = 0; q < 4; q++) {
                    float t = __uint_as_float(afr[mf][q]);
                    afr[mf][q] = __float_as_uint(tf32rn(t));
                }
            }
#pragma unroll
            for (int p = 0; p < 4; p++) {          // B pairs: nf=2p, 2p+1
                uint32_t br[4];
                ldm_x4(br, bb + (uint32_t)(p * 16 * ROWF * 4) + kb);
                bfr[2 * p][0] = br[0]; bfr[2 * p][1] = br[1];
                bfr[2 * p + 1][0] = br[2]; bfr[2 * p + 1][1] = br[3];
            }
#pragma unroll
            for (int mf = 0; mf < 4; mf++)
#pragma unroll
                for (int nf = 0; nf < 8; nf++)
                    mma_tf32(acc[mf][nf], afr[mf], bfr[nf]);
        }
    }

    // ------------------- epilogue: stage through SMEM ---------------------
    __syncthreads();                    // all mma reads of smem done

#pragma unroll
    for (int nf = 0; nf < 8; nf++) {
        const int col = wn * 64 + nf * 8 + 2 * (lane & 3);
#pragma unroll
        for (int mf = 0; mf < 4; mf++) {
            const int row = wm * 64 + mf * 16 + (lane >> 2);
            *reinterpret_cast<float2*>(smem + row * EPI_STRIDE + col) =
                make_float2(acc[mf][nf][0], acc[mf][nf][1]);
            *reinterpret_cast<float2*>(smem + (row + 8) * EPI_STRIDE + col) =
                make_float2(acc[mf][nf][2], acc[mf][nf][3]);
        }
    }
    __syncthreads();

    float* out_h = out;
    float* out_c = out + BH;
    float* out_n = out + 2 * BH;
    float* out_m = out + 3 * BH;

    // reader: row (128 floats = 64 h) per 16 lanes; 4 warps x 2 rows x 16.
    const int ln = lane & 15;
    const int rsub = lane >> 4;
    const int hb = ntile * 64 + 4 * ln;           // global h of this 4-vector
    const float4 bf = *reinterpret_cast<const float4*>(bfv + hb);
    const float4 bc = *reinterpret_cast<const float4*>(bcv + hb);

#pragma unroll
    for (int u = 0; u < 16; u++) {
        const int r = wid * 2 + rsub + 8 * u;     // local row
        const float* sp = smem + r * EPI_STRIDE + 8 * ln;
        float4 q0 = *reinterpret_cast<const float4*>(sp);      // pf0 pc0 pf1 pc1
        float4 q1 = *reinterpret_cast<const float4*>(sp + 4);  // pf2 pc2 pf3 pc3

        const size_t g = (size_t)(m0 + r) * H_DIM + hb;
        float4 mp = *reinterpret_cast<const float4*>(mprev + g);
        float4 cp = *reinterpret_cast<const float4*>(cprev + g);
        float4 np = *reinterpret_cast<const float4*>(nprev + g);

        float4 rh, rc, rn, rm;
        cell(q0.x, q0.y, bf.x, bc.x, mp.x, cp.x, np.x, rh.x, rc.x, rn.x, rm.x);
        cell(q0.z, q0.w, bf.y, bc.y, mp.y, cp.y, np.y, rh.y, rc.y, rn.y, rm.y);
        cell(q1.x, q1.y, bf.z, bc.z, mp.z, cp.z, np.z, rh.z, rc.z, rn.z, rm.z);
        cell(q1.z, q1.w, bf.w, bc.w, mp.w, cp.w, np.w, rh.w, rc.w, rn.w, rm.w);

        *reinterpret_cast<float4*>(out_h + g) = rh;
        *reinterpret_cast<float4*>(out_c + g) = rc;
        *reinterpret_cast<float4*>(out_n + g) = rn;
        *reinterpret_cast<float4*>(out_m + g) = rm;
    }
}

// ------------------------------ launcher -----------------------------------
extern "C" void kernel_launch(void* const* d_in, const int* in_sizes, int n_in,
                              void* d_out, int out_size) {
    const float* x     = (const float*)d_in[0];
    const float* hprev = (const float*)d_in[1];
    const float* cprev = (const float*)d_in[2];
    const float* nprev = (const float*)d_in[3];
    const float* mprev = (const float*)d_in[4];
    const float* wf    = (const float*)d_in[5];
    const float* wc    = (const float*)d_in[6];
    const float* rf    = (const float*)d_in[7];
    const float* rc    = (const float*)d_in[8];
    const float* bf    = (const float*)d_in[9];
    const float* bc    = (const float*)d_in[10];

    cudaFuncSetAttribute(smgu_main,
                         cudaFuncAttributeMaxDynamicSharedMemorySize,
                         SMEM_BYTES);

    prep_weights<<<1024, 256>>>(wf, wc, rf, rc);
    smgu_main<<<4096, 128, SMEM_BYTES>>>(x, hprev, cprev, nprev, mprev,
                                         bf, bc, (float*)d_out);
}

// round 7
// speedup vs baseline: 1.5375x; 1.0726x over previous
#include <cuda_runtime.h>
#include <cuda_fp16.h>
#include <cstdint>
#include <cstddef>

// ---------------------------------------------------------------------------
// sMGU cell: B=65536, IN=256, H=512
// fp16-input mma.sync GEMM [B,768]@[768,1024] (f/c gates interleaved per
// column pair), fp32 accumulate, fused elementwise epilogue.
// R6: tf32 legacy mma is half-rate (R4/R5 both pinned at tensor=50%);
// fp16 has the SAME mantissa width as tf32 (eps 2^-11) and our operands are
// range-safe, so fp16 doubles the MMA rate at zero precision cost. Inputs
// are pre-rounded to fp16 in prep passes (also halves SMEM/LDS/cp.async).
// ---------------------------------------------------------------------------

#define H_DIM   512
#define BH      33554432ull            // B*H
#define KTOT    768
#define KC      32                     // k-chunk (halves)
#define NCHUNK  24                     // 768/32
#define NSTAGE  3
#define ROWH    40                     // smem row stride in halves (pad 32->40)
#define ROWB    (ROWH * 2)             // 80 bytes: 5 mod 8 wide-banks -> clean
#define STG_B   (2 * 128 * ROWB)       // bytes per stage (A + B tiles) = 20480
#define EPI_STRIDE 132                 // epilogue smem row stride (floats)
#define SMEM_BYTES (EPI_STRIDE * 128 * 4)  // 67584 >= 3*STG_B (61440)

// fp16 operands (RN-rounded once in prep).
// g_Ah[row][k]: k<256 = x[row], k>=256 = h_prev[row].
// g_Wth[n][k]:  h = n>>1, gate = n&1 (0=f, 1=c).
__device__ __half g_Ah [65536ull * KTOT];
__device__ __half g_Wth[1024 * KTOT];

// ------------------------------- helpers -----------------------------------
__device__ __forceinline__ uint32_t smem_u32(const void* p) {
    uint32_t a;
    asm("{ .reg .u64 t; cvta.to.shared.u64 t, %1; cvt.u32.u64 %0, t; }"
        : "=r"(a) : "l"(p));
    return a;
}
__device__ __forceinline__ void cp16(uint32_t dst, const void* src) {
    asm volatile("cp.async.cg.shared.global [%0], [%1], 16;"
                 :: "r"(dst), "l"(src));
}
__device__ __forceinline__ void ldm_x4(uint32_t* r, uint32_t addr) {
    asm volatile("ldmatrix.sync.aligned.m8n8.x4.shared.b16 {%0,%1,%2,%3}, [%4];"
                 : "=r"(r[0]), "=r"(r[1]), "=r"(r[2]), "=r"(r[3]) : "r"(addr));
}
__device__ __forceinline__ void mma_f16(float* d, const uint32_t* a,
                                        const uint32_t* b) {
    asm volatile(
        "mma.sync.aligned.m16n8k16.row.col.f32.f16.f16.f32 "
        "{%0,%1,%2,%3}, {%4,%5,%6,%7}, {%8,%9}, {%0,%1,%2,%3};"
        : "+f"(d[0]), "+f"(d[1]), "+f"(d[2]), "+f"(d[3])
        : "r"(a[0]), "r"(a[1]), "r"(a[2]), "r"(a[3]), "r"(b[0]), "r"(b[1]));
}

__device__ __forceinline__ float tanh_fast(float v) {
    float e = __expf(2.0f * v);
    return 1.0f - __fdividef(2.0f, e + 1.0f);
}
__device__ __forceinline__ void cell(float df, float dc, float bfe, float bce,
                                     float mpv, float cpv, float npv,
                                     float& h, float& c, float& n, float& m) {
    float a  = df + bfe + mpv;              // log f_t + m_prev
    m = fmaxf(a, 0.0f);
    float e  = __expf(-fabsf(a));           // one exp covers both branches
    float fp = (a >= 0.0f) ? 1.0f : e;      // exp(a - m)
    float ip = (a >= 0.0f) ? e : 1.0f;      // exp(-m)
    float th = tanh_fast(dc + bce);
    c = fp * cpv + ip * th;
    n = fp * npv + ip;
    h = tanh_fast(__fdividef(c, fmaxf(n, 1e-8f)));
}

// ------------------------------ prep kernels -------------------------------
__global__ void prep_weights(const float* __restrict__ wf,
                             const float* __restrict__ wc,
                             const float* __restrict__ rf,
                             const float* __restrict__ rc) {
    int n = blockIdx.x;                 // 0..1023
    int h = n >> 1, gate = n & 1;
    const float* W = gate ? wc : wf;
    const float* R = gate ? rc : rf;
    for (int k = threadIdx.x; k < KTOT; k += blockDim.x) {
        float v = (k < 256) ? W[(size_t)k * H_DIM + h]
                            : R[(size_t)(k - 256) * H_DIM + h];
        g_Wth[(size_t)n * KTOT + k] = __float2half_rn(v);
    }
}

// one thread = 8 halves of g_Ah (16B store)
__global__ void prep_act(const float4* __restrict__ x4,
                         const float4* __restrict__ h4) {
    size_t idx = (size_t)blockIdx.x * blockDim.x + threadIdx.x;
    size_t row = idx / 96;
    int    q   = (int)(idx % 96);       // 8-half group; k0 = q*8
    float4 a, b;
    if (q < 32) {                       // from x
        a = x4[row * 64 + q * 2];
        b = x4[row * 64 + q * 2 + 1];
    } else {                            // from h_prev
        a = h4[row * 128 + (q - 32) * 2];
        b = h4[row * 128 + (q - 32) * 2 + 1];
    }
    __half2 p0 = __float22half2_rn(make_float2(a.x, a.y));
    __half2 p1 = __float22half2_rn(make_float2(a.z, a.w));
    __half2 p2 = __float22half2_rn(make_float2(b.x, b.y));
    __half2 p3 = __float22half2_rn(make_float2(b.z, b.w));
    uint4 v;
    v.x = *reinterpret_cast<uint32_t*>(&p0);
    v.y = *reinterpret_cast<uint32_t*>(&p1);
    v.z = *reinterpret_cast<uint32_t*>(&p2);
    v.w = *reinterpret_cast<uint32_t*>(&p3);
    reinterpret_cast<uint4*>(g_Ah)[idx] = v;
}

// ------------------------------ main kernel --------------------------------
// CTA 128 rows x 128 cols. 4 warps, (wm 0..1) x (wn 0..1), warp tile 64x64.
extern "C" __global__ void __launch_bounds__(128, 2)
smgu_main(const float* __restrict__ cprev, const float* __restrict__ nprev,
          const float* __restrict__ mprev, const float* __restrict__ bfv,
          const float* __restrict__ bcv,   float* __restrict__ out) {
    extern __shared__ float smem[];
    const int tid  = threadIdx.x;
    const int lane = tid & 31, wid = tid >> 5;
    const int wm   = wid & 1,  wn  = wid >> 1;
    const int mtile = (int)blockIdx.x >> 3;
    const int ntile = (int)blockIdx.x & 7;
    const int m0  = mtile * 128;
    const int ncb = ntile * 128;

    const uint32_t sbase = smem_u32(smem);
    const __half* __restrict__ asrc0 = g_Ah  + (size_t)m0  * KTOT;
    const __half* __restrict__ bsrc0 = g_Wth + (size_t)ncb * KTOT;

    float acc[4][8][4];                  // mf x nf x frag = 128 regs
#pragma unroll
    for (int i = 0; i < 4; i++)
#pragma unroll
        for (int j = 0; j < 8; j++)
#pragma unroll
            for (int r = 0; r < 4; r++) acc[i][j][r] = 0.0f;

    // loader: chunk c -> stage s. A 128x32h + B 128x32h; 4+4 cp16/thread.
    // row = tid, seg = u: warp lanes hit 8 distinct 16B banks (5r mod 8).
    auto load = [&](int c, int s) {
        const uint32_t abase = sbase + (uint32_t)(s * STG_B);
        const uint32_t bbase = abase + (uint32_t)(128 * ROWB);
        const __half* ap = asrc0 + c * KC;
        const __half* bp = bsrc0 + c * KC;
        const uint32_t doff = (uint32_t)tid * ROWB;
#pragma unroll
        for (int u = 0; u < 4; u++)
            cp16(abase + doff + u * 16, ap + (size_t)tid * KTOT + u * 8);
#pragma unroll
        for (int u = 0; u < 4; u++)
            cp16(bbase + doff + u * 16, bp + (size_t)tid * KTOT + u * 8);
        asm volatile("cp.async.commit_group;" ::: "memory");
    };

    load(0, 0);
    load(1, 1);

    // ldmatrix per-thread base offsets (bytes, within a stage)
    // A x4 tiles: a0..a3; lanes 0-15 -> rows (lane&15) @k0; 16-31 -> @k8.
    const uint32_t a_off = (uint32_t)((wm * 64 + (lane & 15)) * ROWB
                                      + (lane >> 4) * 16);
    // B x4 tiles: (nf even b0, b1, nf odd b0, b1);
    // lanes: 0-7 n-rows @k0; 8-15 same rows @k8; 16-23 rows+8 @k0; 24-31 +8 @k8.
    const uint32_t b_off = (uint32_t)(128 * ROWB
                                      + (wn * 64 + ((lane >> 4) << 3)
                                         + (lane & 7)) * ROWB
                                      + ((lane >> 3) & 1) * 16);

    for (int c = 0; c < NCHUNK; c++) {
        const int s = c % NSTAGE;
        asm volatile("cp.async.wait_group 1;" ::: "memory");
        __syncthreads();   // all warps have chunk c; all done reading c-1

        if (c + 2 < NCHUNK) load(c + 2, (c + 2) % NSTAGE);  // stage of c-1
        else asm volatile("cp.async.commit_group;" ::: "memory");

        const uint32_t stg = sbase + (uint32_t)(s * STG_B);
        const uint32_t ab  = stg + a_off;
        const uint32_t bb  = stg + b_off;
#pragma unroll
        for (int kk = 0; kk < 2; kk++) {             // two k16 steps
            const uint32_t kb = (uint32_t)(kk * 32); // 16 halves
            uint32_t afr[4][4], bfr[8][2];
#pragma unroll
            for (int mf = 0; mf < 4; mf++)
                ldm_x4(afr[mf], ab + (uint32_t)(mf * 16 * ROWB) + kb);
#pragma unroll
            for (int p = 0; p < 4; p++) {            // B pairs: nf=2p, 2p+1
                uint32_t br[4];
                ldm_x4(br, bb + (uint32_t)(p * 16 * ROWB) + kb);
                bfr[2 * p][0] = br[0]; bfr[2 * p][1] = br[1];
                bfr[2 * p + 1][0] = br[2]; bfr[2 * p + 1][1] = br[3];
            }
#pragma unroll
            for (int mf = 0; mf < 4; mf++)
#pragma unroll
                for (int nf = 0; nf < 8; nf++)
                    mma_f16(acc[mf][nf], afr[mf], bfr[nf]);
        }
    }

    // ------------------- epilogue: stage through SMEM ---------------------
    __syncthreads();                    // all mma reads of smem done

#pragma unroll
    for (int nf = 0; nf < 8; nf++) {
        const int col = wn * 64 + nf * 8 + 2 * (lane & 3);
#pragma unroll
        for (int mf = 0; mf < 4; mf++) {
            const int row = wm * 64 + mf * 16 + (lane >> 2);
            *reinterpret_cast<float2*>(smem + row * EPI_STRIDE + col) =
                make_float2(acc[mf][nf][0], acc[mf][nf][1]);
            *reinterpret_cast<float2*>(smem + (row + 8) * EPI_STRIDE + col) =
                make_float2(acc[mf][nf][2], acc[mf][nf][3]);
        }
    }
    __syncthreads();

    float* out_h = out;
    float* out_c = out + BH;
    float* out_n = out + 2 * BH;
    float* out_m = out + 3 * BH;

    // reader: row (128 floats = 64 h) per 16 lanes; 4 warps x 2 rows x 16.
    const int ln = lane & 15;
    const int rsub = lane >> 4;
    const int hb = ntile * 64 + 4 * ln;           // global h of this 4-vector
    const float4 bf = *reinterpret_cast<const float4*>(bfv + hb);
    const float4 bc = *reinterpret_cast<const float4*>(bcv + hb);

#pragma unroll
    for (int u = 0; u < 16; u++) {
        const int r = wid * 2 + rsub + 8 * u;     // local row
        const float* sp = smem + r * EPI_STRIDE + 8 * ln;
        float4 q0 = *reinterpret_cast<const float4*>(sp);      // pf0 pc0 pf1 pc1
        float4 q1 = *reinterpret_cast<const float4*>(sp + 4);  // pf2 pc2 pf3 pc3

        const size_t g = (size_t)(m0 + r) * H_DIM + hb;
        float4 mp = *reinterpret_cast<const float4*>(mprev + g);
        float4 cp = *reinterpret_cast<const float4*>(cprev + g);
        float4 np = *reinterpret_cast<const float4*>(nprev + g);

        float4 rh, rc, rn, rm;
        cell(q0.x, q0.y, bf.x, bc.x, mp.x, cp.x, np.x, rh.x, rc.x, rn.x, rm.x);
        cell(q0.z, q0.w, bf.y, bc.y, mp.y, cp.y, np.y, rh.y, rc.y, rn.y, rm.y);
        cell(q1.x, q1.y, bf.z, bc.z, mp.z, cp.z, np.z, rh.z, rc.z, rn.z, rm.z);
        cell(q1.z, q1.w, bf.w, bc.w, mp.w, cp.w, np.w, rh.w, rc.w, rn.w, rm.w);

        *reinterpret_cast<float4*>(out_h + g) = rh;
        *reinterpret_cast<float4*>(out_c + g) = rc;
        *reinterpret_cast<float4*>(out_n + g) = rn;
        *reinterpret_cast<float4*>(out_m + g) = rm;
    }
}

// ------------------------------ launcher -----------------------------------
extern "C" void kernel_launch(void* const* d_in, const int* in_sizes, int n_in,
                              void* d_out, int out_size) {
    const float* x     = (const float*)d_in[0];
    const float* hprev = (const float*)d_in[1];
    const float* cprev = (const float*)d_in[2];
    const float* nprev = (const float*)d_in[3];
    const float* mprev = (const float*)d_in[4];
    const float* wf    = (const float*)d_in[5];
    const float* wc    = (const float*)d_in[6];
    const float* rf    = (const float*)d_in[7];
    const float* rc    = (const float*)d_in[8];
    const float* bf    = (const float*)d_in[9];
    const float* bc    = (const float*)d_in[10];

    cudaFuncSetAttribute(smgu_main,
                         cudaFuncAttributeMaxDynamicSharedMemorySize,
                         SMEM_BYTES);

    prep_weights<<<1024, 256>>>(wf, wc, rf, rc);
    prep_act<<<24576, 256>>>((const float4*)x, (const float4*)hprev);
    smgu_main<<<4096, 128, SMEM_BYTES>>>(cprev, nprev, mprev,
                                         bf, bc, (float*)d_out);
}

// round 8
// speedup vs baseline: 1.6429x; 1.0685x over previous
#include <cuda_runtime.h>
#include <cuda_fp16.h>
#include <cstdint>
#include <cstddef>

// ---------------------------------------------------------------------------
// sMGU cell: B=65536, IN=256, H=512
// fp16-input mma.sync GEMM [B,768]@[768,1024] (f/c gates interleaved per
// column pair), fp32 accumulate, fused elementwise epilogue.
// R7: 3 CTAs/SM (launch_bounds(128,3)) so epilogue phases overlap tensor
// phases of sibling CTAs; inner loop streams B fragments (4 live regs
// instead of 16) to fit the 170-register budget without spilling acc.
// ---------------------------------------------------------------------------

#define H_DIM   512
#define BH      33554432ull            // B*H
#define KTOT    768
#define KC      32                     // k-chunk (halves)
#define NCHUNK  24                     // 768/32
#define NSTAGE  3
#define ROWH    40                     // smem row stride in halves (pad 32->40)
#define ROWB    (ROWH * 2)             // 80 bytes
#define STG_B   (2 * 128 * ROWB)       // bytes per stage (A + B tiles) = 20480
#define EPI_STRIDE 132                 // epilogue smem row stride (floats)
#define SMEM_BYTES (EPI_STRIDE * 128 * 4)  // 67584 >= 3*STG_B (61440)

// fp16 operands (RN-rounded once in prep).
// g_Ah[row][k]: k<256 = x[row], k>=256 = h_prev[row].
// g_Wth[n][k]:  h = n>>1, gate = n&1 (0=f, 1=c).
__device__ __half g_Ah [65536ull * KTOT];
__device__ __half g_Wth[1024 * KTOT];

// ------------------------------- helpers -----------------------------------
__device__ __forceinline__ uint32_t smem_u32(const void* p) {
    uint32_t a;
    asm("{ .reg .u64 t; cvta.to.shared.u64 t, %1; cvt.u32.u64 %0, t; }"
        : "=r"(a) : "l"(p));
    return a;
}
__device__ __forceinline__ void cp16(uint32_t dst, const void* src) {
    asm volatile("cp.async.cg.shared.global [%0], [%1], 16;"
                 :: "r"(dst), "l"(src));
}
__device__ __forceinline__ void ldm_x4(uint32_t* r, uint32_t addr) {
    asm volatile("ldmatrix.sync.aligned.m8n8.x4.shared.b16 {%0,%1,%2,%3}, [%4];"
                 : "=r"(r[0]), "=r"(r[1]), "=r"(r[2]), "=r"(r[3]) : "r"(addr));
}
__device__ __forceinline__ void mma_f16(float* d, const uint32_t* a,
                                        const uint32_t* b) {
    asm volatile(
        "mma.sync.aligned.m16n8k16.row.col.f32.f16.f16.f32 "
        "{%0,%1,%2,%3}, {%4,%5,%6,%7}, {%8,%9}, {%0,%1,%2,%3};"
        : "+f"(d[0]), "+f"(d[1]), "+f"(d[2]), "+f"(d[3])
        : "r"(a[0]), "r"(a[1]), "r"(a[2]), "r"(a[3]), "r"(b[0]), "r"(b[1]));
}

__device__ __forceinline__ float tanh_fast(float v) {
    float e = __expf(2.0f * v);
    return 1.0f - __fdividef(2.0f, e + 1.0f);
}
__device__ __forceinline__ void cell(float df, float dc, float bfe, float bce,
                                     float mpv, float cpv, float npv,
                                     float& h, float& c, float& n, float& m) {
    float a  = df + bfe + mpv;              // log f_t + m_prev
    m = fmaxf(a, 0.0f);
    float e  = __expf(-fabsf(a));           // one exp covers both branches
    float fp = (a >= 0.0f) ? 1.0f : e;      // exp(a - m)
    float ip = (a >= 0.0f) ? e : 1.0f;      // exp(-m)
    float th = tanh_fast(dc + bce);
    c = fp * cpv + ip * th;
    n = fp * npv + ip;
    h = tanh_fast(__fdividef(c, fmaxf(n, 1e-8f)));
}

// ------------------------------ prep kernels -------------------------------
__global__ void prep_weights(const float* __restrict__ wf,
                             const float* __restrict__ wc,
                             const float* __restrict__ rf,
                             const float* __restrict__ rc) {
    int n = blockIdx.x;                 // 0..1023
    int h = n >> 1, gate = n & 1;
    const float* W = gate ? wc : wf;
    const float* R = gate ? rc : rf;
    for (int k = threadIdx.x; k < KTOT; k += blockDim.x) {
        float v = (k < 256) ? W[(size_t)k * H_DIM + h]
                            : R[(size_t)(k - 256) * H_DIM + h];
        g_Wth[(size_t)n * KTOT + k] = __float2half_rn(v);
    }
}

// one thread = 8 halves of g_Ah (16B store)
__global__ void prep_act(const float4* __restrict__ x4,
                         const float4* __restrict__ h4) {
    size_t idx = (size_t)blockIdx.x * blockDim.x + threadIdx.x;
    size_t row = idx / 96;
    int    q   = (int)(idx % 96);       // 8-half group; k0 = q*8
    float4 a, b;
    if (q < 32) {                       // from x
        a = x4[row * 64 + q * 2];
        b = x4[row * 64 + q * 2 + 1];
    } else {                            // from h_prev
        a = h4[row * 128 + (q - 32) * 2];
        b = h4[row * 128 + (q - 32) * 2 + 1];
    }
    __half2 p0 = __float22half2_rn(make_float2(a.x, a.y));
    __half2 p1 = __float22half2_rn(make_float2(a.z, a.w));
    __half2 p2 = __float22half2_rn(make_float2(b.x, b.y));
    __half2 p3 = __float22half2_rn(make_float2(b.z, b.w));
    uint4 v;
    v.x = *reinterpret_cast<uint32_t*>(&p0);
    v.y = *reinterpret_cast<uint32_t*>(&p1);
    v.z = *reinterpret_cast<uint32_t*>(&p2);
    v.w = *reinterpret_cast<uint32_t*>(&p3);
    reinterpret_cast<uint4*>(g_Ah)[idx] = v;
}

// ------------------------------ main kernel --------------------------------
// CTA 128 rows x 128 cols. 4 warps, (wm 0..1) x (wn 0..1), warp tile 64x64.
extern "C" __global__ void __launch_bounds__(128, 3)
smgu_main(const float* __restrict__ cprev, const float* __restrict__ nprev,
          const float* __restrict__ mprev, const float* __restrict__ bfv,
          const float* __restrict__ bcv,   float* __restrict__ out) {
    extern __shared__ float smem[];
    const int tid  = threadIdx.x;
    const int lane = tid & 31, wid = tid >> 5;
    const int wm   = wid & 1,  wn  = wid >> 1;
    const int mtile = (int)blockIdx.x >> 3;
    const int ntile = (int)blockIdx.x & 7;
    const int m0  = mtile * 128;
    const int ncb = ntile * 128;

    const uint32_t sbase = smem_u32(smem);

    // incremental gmem pointers for the loader (advance by KC per chunk)
    const __half* aptr = g_Ah  + ((size_t)m0  + tid) * KTOT;
    const __half* bptr = g_Wth + ((size_t)ncb + tid) * KTOT;

    float acc[4][8][4];                  // mf x nf x frag = 128 regs
#pragma unroll
    for (int i = 0; i < 4; i++)
#pragma unroll
        for (int j = 0; j < 8; j++)
#pragma unroll
            for (int r = 0; r < 4; r++) acc[i][j][r] = 0.0f;

    // loader: chunk tail of aptr/bptr -> stage s. 4+4 cp16 per thread.
    auto load = [&](int s) {
        const uint32_t abase = sbase + (uint32_t)(s * STG_B)
                             + (uint32_t)tid * ROWB;
        const uint32_t bbase = abase + (uint32_t)(128 * ROWB);
#pragma unroll
        for (int u = 0; u < 4; u++)
            cp16(abase + u * 16, aptr + u * 8);
#pragma unroll
        for (int u = 0; u < 4; u++)
            cp16(bbase + u * 16, bptr + u * 8);
        asm volatile("cp.async.commit_group;" ::: "memory");
        aptr += KC; bptr += KC;
    };

    load(0);
    load(1);

    // ldmatrix per-thread base offsets (bytes, within a stage)
    const uint32_t a_off = (uint32_t)((wm * 64 + (lane & 15)) * ROWB
                                      + (lane >> 4) * 16);
    const uint32_t b_off = (uint32_t)(128 * ROWB
                                      + (wn * 64 + ((lane >> 4) << 3)
                                         + (lane & 7)) * ROWB
                                      + ((lane >> 3) & 1) * 16);

    for (int c = 0; c < NCHUNK; c++) {
        const int s = c % NSTAGE;
        asm volatile("cp.async.wait_group 1;" ::: "memory");
        __syncthreads();   // all warps have chunk c; all done reading c-1

        if (c + 2 < NCHUNK) load((c + 2) % NSTAGE);     // stage of c-1
        else asm volatile("cp.async.commit_group;" ::: "memory");

        const uint32_t stg = sbase + (uint32_t)(s * STG_B);
        const uint32_t ab  = stg + a_off;
        const uint32_t bb  = stg + b_off;
#pragma unroll
        for (int kk = 0; kk < 2; kk++) {             // two k16 steps
            const uint32_t kb = (uint32_t)(kk * 32); // 16 halves
            uint32_t afr[4][4];
#pragma unroll
            for (int mf = 0; mf < 4; mf++)
                ldm_x4(afr[mf], ab + (uint32_t)(mf * 16 * ROWB) + kb);
#pragma unroll
            for (int p = 0; p < 4; p++) {            // stream B pairs
                uint32_t br[4];
                ldm_x4(br, bb + (uint32_t)(p * 16 * ROWB) + kb);
#pragma unroll
                for (int mf = 0; mf < 4; mf++) {
                    mma_f16(acc[mf][2 * p],     afr[mf], br);
                    mma_f16(acc[mf][2 * p + 1], afr[mf], br + 2);
                }
            }
        }
    }

    // ------------------- epilogue: stage through SMEM ---------------------
    __syncthreads();                    // all mma reads of smem done

#pragma unroll
    for (int nf = 0; nf < 8; nf++) {
        const int col = wn * 64 + nf * 8 + 2 * (lane & 3);
#pragma unroll
        for (int mf = 0; mf < 4; mf++) {
            const int row = wm * 64 + mf * 16 + (lane >> 2);
            *reinterpret_cast<float2*>(smem + row * EPI_STRIDE + col) =
                make_float2(acc[mf][nf][0], acc[mf][nf][1]);
            *reinterpret_cast<float2*>(smem + (row + 8) * EPI_STRIDE + col) =
                make_float2(acc[mf][nf][2], acc[mf][nf][3]);
        }
    }
    __syncthreads();

    float* out_h = out;
    float* out_c = out + BH;
    float* out_n = out + 2 * BH;
    float* out_m = out + 3 * BH;

    // reader: row (128 floats = 64 h) per 16 lanes; 4 warps x 2 rows x 16.
    const int ln = lane & 15;
    const int rsub = lane >> 4;
    const int hb = ntile * 64 + 4 * ln;           // global h of this 4-vector
    const float4 bf = *reinterpret_cast<const float4*>(bfv + hb);
    const float4 bc = *reinterpret_cast<const float4*>(bcv + hb);

#pragma unroll
    for (int u = 0; u < 16; u++) {
        const int r = wid * 2 + rsub + 8 * u;     // local row
        const float* sp = smem + r * EPI_STRIDE + 8 * ln;
        float4 q0 = *reinterpret_cast<const float4*>(sp);      // pf0 pc0 pf1 pc1
        float4 q1 = *reinterpret_cast<const float4*>(sp + 4);  // pf2 pc2 pf3 pc3

        const size_t g = (size_t)(m0 + r) * H_DIM + hb;
        float4 mp = *reinterpret_cast<const float4*>(mprev + g);
        float4 cp = *reinterpret_cast<const float4*>(cprev + g);
        float4 np = *reinterpret_cast<const float4*>(nprev + g);

        float4 rh, rc, rn, rm;
        cell(q0.x, q0.y, bf.x, bc.x, mp.x, cp.x, np.x, rh.x, rc.x, rn.x, rm.x);
        cell(q0.z, q0.w, bf.y, bc.y, mp.y, cp.y, np.y, rh.y, rc.y, rn.y, rm.y);
        cell(q1.x, q1.y, bf.z, bc.z, mp.z, cp.z, np.z, rh.z, rc.z, rn.z, rm.z);
        cell(q1.z, q1.w, bf.w, bc.w, mp.w, cp.w, np.w, rh.w, rc.w, rn.w, rm.w);

        *reinterpret_cast<float4*>(out_h + g) = rh;
        *reinterpret_cast<float4*>(out_c + g) = rc;
        *reinterpret_cast<float4*>(out_n + g) = rn;
        *reinterpret_cast<float4*>(out_m + g) = rm;
    }
}

// ------------------------------ launcher -----------------------------------
extern "C" void kernel_launch(void* const* d_in, const int* in_sizes, int n_in,
                              void* d_out, int out_size) {
    const float* x     = (const float*)d_in[0];
    const float* hprev = (const float*)d_in[1];
    const float* cprev = (const float*)d_in[2];
    const float* nprev = (const float*)d_in[3];
    const float* mprev = (const float*)d_in[4];
    const float* wf    = (const float*)d_in[5];
    const float* wc    = (const float*)d_in[6];
    const float* rf    = (const float*)d_in[7];
    const float* rc    = (const float*)d_in[8];
    const float* bf    = (const float*)d_in[9];
    const float* bc    = (const float*)d_in[10];

    cudaFuncSetAttribute(smgu_main,
                         cudaFuncAttributeMaxDynamicSharedMemorySize,
                         SMEM_BYTES);

    prep_weights<<<1024, 256>>>(wf, wc, rf, rc);
    prep_act<<<24576, 256>>>((const float4*)x, (const float4*)hprev);
    smgu_main<<<4096, 128, SMEM_BYTES>>>(cprev, nprev, mprev,
                                         bf, bc, (float*)d_out);
}

// round 9
// speedup vs baseline: 2.0413x; 1.2425x over previous
#include <cuda_runtime.h>
#include <cuda_fp16.h>
#include <cstdint>
#include <cstddef>

// ---------------------------------------------------------------------------
// sMGU cell: B=65536, IN=256, H=512
// fp16-input mma.sync GEMM [B,768]@[768,1024] (f/c gates interleaved per
// column pair), fp32 accumulate, fused elementwise epilogue.
// R8: 8 warps/CTA (256 thr), warp tile 64x32, 2 CTAs/SM -> 16 warps/SM.
// R6->R7 showed occupancy is the binding resource; fp16 removed the SMEM
// crossbar pressure that made this geometry co-bound back in R4.
// ---------------------------------------------------------------------------

#define H_DIM   512
#define BH      33554432ull            // B*H
#define KTOT    768
#define KC      32                     // k-chunk (halves)
#define NCHUNK  24                     // 768/32
#define NSTAGE  3
#define ROWH    40                     // smem row stride in halves (pad 32->40)
#define ROWB    (ROWH * 2)             // 80 bytes
#define STG_B   (2 * 128 * ROWB)       // bytes per stage (A + B tiles) = 20480
#define EPI_STRIDE 132                 // epilogue smem row stride (floats)
#define SMEM_BYTES (EPI_STRIDE * 128 * 4)  // 67584 >= 3*STG_B (61440)

// fp16 operands (RN-rounded once in prep).
// g_Ah[row][k]: k<256 = x[row], k>=256 = h_prev[row].
// g_Wth[n][k]:  h = n>>1, gate = n&1 (0=f, 1=c).
__device__ __half g_Ah [65536ull * KTOT];
__device__ __half g_Wth[1024 * KTOT];

// ------------------------------- helpers -----------------------------------
__device__ __forceinline__ uint32_t smem_u32(const void* p) {
    uint32_t a;
    asm("{ .reg .u64 t; cvta.to.shared.u64 t, %1; cvt.u32.u64 %0, t; }"
        : "=r"(a) : "l"(p));
    return a;
}
__device__ __forceinline__ void cp16(uint32_t dst, const void* src) {
    asm volatile("cp.async.cg.shared.global [%0], [%1], 16;"
                 :: "r"(dst), "l"(src));
}
__device__ __forceinline__ void ldm_x4(uint32_t* r, uint32_t addr) {
    asm volatile("ldmatrix.sync.aligned.m8n8.x4.shared.b16 {%0,%1,%2,%3}, [%4];"
                 : "=r"(r[0]), "=r"(r[1]), "=r"(r[2]), "=r"(r[3]) : "r"(addr));
}
__device__ __forceinline__ void mma_f16(float* d, const uint32_t* a,
                                        const uint32_t* b) {
    asm volatile(
        "mma.sync.aligned.m16n8k16.row.col.f32.f16.f16.f32 "
        "{%0,%1,%2,%3}, {%4,%5,%6,%7}, {%8,%9}, {%0,%1,%2,%3};"
        : "+f"(d[0]), "+f"(d[1]), "+f"(d[2]), "+f"(d[3])
        : "r"(a[0]), "r"(a[1]), "r"(a[2]), "r"(a[3]), "r"(b[0]), "r"(b[1]));
}

__device__ __forceinline__ float tanh_fast(float v) {
    float e = __expf(2.0f * v);
    return 1.0f - __fdividef(2.0f, e + 1.0f);
}
__device__ __forceinline__ void cell(float df, float dc, float bfe, float bce,
                                     float mpv, float cpv, float npv,
                                     float& h, float& c, float& n, float& m) {
    float a  = df + bfe + mpv;              // log f_t + m_prev
    m = fmaxf(a, 0.0f);
    float e  = __expf(-fabsf(a));           // one exp covers both branches
    float fp = (a >= 0.0f) ? 1.0f : e;      // exp(a - m)
    float ip = (a >= 0.0f) ? e : 1.0f;      // exp(-m)
    float th = tanh_fast(dc + bce);
    c = fp * cpv + ip * th;
    n = fp * npv + ip;
    h = tanh_fast(__fdividef(c, fmaxf(n, 1e-8f)));
}

// ------------------------------ prep kernels -------------------------------
__global__ void prep_weights(const float* __restrict__ wf,
                             const float* __restrict__ wc,
                             const float* __restrict__ rf,
                             const float* __restrict__ rc) {
    int n = blockIdx.x;                 // 0..1023
    int h = n >> 1, gate = n & 1;
    const float* W = gate ? wc : wf;
    const float* R = gate ? rc : rf;
    for (int k = threadIdx.x; k < KTOT; k += blockDim.x) {
        float v = (k < 256) ? W[(size_t)k * H_DIM + h]
                            : R[(size_t)(k - 256) * H_DIM + h];
        g_Wth[(size_t)n * KTOT + k] = __float2half_rn(v);
    }
}

// one thread = 8 halves of g_Ah (16B store)
__global__ void prep_act(const float4* __restrict__ x4,
                         const float4* __restrict__ h4) {
    size_t idx = (size_t)blockIdx.x * blockDim.x + threadIdx.x;
    size_t row = idx / 96;
    int    q   = (int)(idx % 96);       // 8-half group; k0 = q*8
    float4 a, b;
    if (q < 32) {                       // from x
        a = x4[row * 64 + q * 2];
        b = x4[row * 64 + q * 2 + 1];
    } else {                            // from h_prev
        a = h4[row * 128 + (q - 32) * 2];
        b = h4[row * 128 + (q - 32) * 2 + 1];
    }
    __half2 p0 = __float22half2_rn(make_float2(a.x, a.y));
    __half2 p1 = __float22half2_rn(make_float2(a.z, a.w));
    __half2 p2 = __float22half2_rn(make_float2(b.x, b.y));
    __half2 p3 = __float22half2_rn(make_float2(b.z, b.w));
    uint4 v;
    v.x = *reinterpret_cast<uint32_t*>(&p0);
    v.y = *reinterpret_cast<uint32_t*>(&p1);
    v.z = *reinterpret_cast<uint32_t*>(&p2);
    v.w = *reinterpret_cast<uint32_t*>(&p3);
    reinterpret_cast<uint4*>(g_Ah)[idx] = v;
}

// ------------------------------ main kernel --------------------------------
// CTA 128 rows x 128 cols. 8 warps, (wm 0..1) x (wn 0..3), warp tile 64x32.
extern "C" __global__ void __launch_bounds__(256, 2)
smgu_main(const float* __restrict__ cprev, const float* __restrict__ nprev,
          const float* __restrict__ mprev, const float* __restrict__ bfv,
          const float* __restrict__ bcv,   float* __restrict__ out) {
    extern __shared__ float smem[];
    const int tid  = threadIdx.x;
    const int lane = tid & 31, wid = tid >> 5;
    const int wm   = wid & 1,  wn  = wid >> 1;
    const int mtile = (int)blockIdx.x >> 3;
    const int ntile = (int)blockIdx.x & 7;
    const int m0  = mtile * 128;
    const int ncb = ntile * 128;

    const uint32_t sbase = smem_u32(smem);

    // incremental gmem pointers for the loader (advance by KC per chunk).
    // thread t loads row t>>1, segment pair (t&1): 2 cp16 for A, 2 for B.
    const int lrow = tid >> 1, lseg = tid & 1;
    const __half* aptr = g_Ah  + ((size_t)(m0  + lrow)) * KTOT + lseg * 16;
    const __half* bptr = g_Wth + ((size_t)(ncb + lrow)) * KTOT + lseg * 16;
    const uint32_t ldoff = (uint32_t)lrow * ROWB + (uint32_t)lseg * 32;

    float acc[4][4][4];                  // mf x nf x frag = 64 regs
#pragma unroll
    for (int i = 0; i < 4; i++)
#pragma unroll
        for (int j = 0; j < 4; j++)
#pragma unroll
            for (int r = 0; r < 4; r++) acc[i][j][r] = 0.0f;

    auto load = [&](int s) {
        const uint32_t abase = sbase + (uint32_t)(s * STG_B) + ldoff;
        const uint32_t bbase = abase + (uint32_t)(128 * ROWB);
        cp16(abase,      aptr);
        cp16(abase + 16, aptr + 8);
        cp16(bbase,      bptr);
        cp16(bbase + 16, bptr + 8);
        asm volatile("cp.async.commit_group;" ::: "memory");
        aptr += KC; bptr += KC;
    };

    load(0);
    load(1);

    // ldmatrix per-thread base offsets (bytes, within a stage)
    const uint32_t a_off = (uint32_t)((wm * 64 + (lane & 15)) * ROWB
                                      + (lane >> 4) * 16);
    const uint32_t b_off = (uint32_t)(128 * ROWB
                                      + (wn * 32 + ((lane >> 4) << 3)
                                         + (lane & 7)) * ROWB
                                      + ((lane >> 3) & 1) * 16);

    for (int c = 0; c < NCHUNK; c++) {
        const int s = c % NSTAGE;
        asm volatile("cp.async.wait_group 1;" ::: "memory");
        __syncthreads();   // all warps have chunk c; all done reading c-1

        if (c + 2 < NCHUNK) load((c + 2) % NSTAGE);     // stage of c-1
        else asm volatile("cp.async.commit_group;" ::: "memory");

        const uint32_t stg = sbase + (uint32_t)(s * STG_B);
        const uint32_t ab  = stg + a_off;
        const uint32_t bb  = stg + b_off;
#pragma unroll
        for (int kk = 0; kk < 2; kk++) {             // two k16 steps
            const uint32_t kb = (uint32_t)(kk * 32); // 16 halves
            uint32_t afr[4][4];
#pragma unroll
            for (int mf = 0; mf < 4; mf++)
                ldm_x4(afr[mf], ab + (uint32_t)(mf * 16 * ROWB) + kb);
#pragma unroll
            for (int p = 0; p < 2; p++) {            // stream B pairs
                uint32_t br[4];
                ldm_x4(br, bb + (uint32_t)(p * 16 * ROWB) + kb);
#pragma unroll
                for (int mf = 0; mf < 4; mf++) {
                    mma_f16(acc[mf][2 * p],     afr[mf], br);
                    mma_f16(acc[mf][2 * p + 1], afr[mf], br + 2);
                }
            }
        }
    }

    // ------------------- epilogue: stage through SMEM ---------------------
    __syncthreads();                    // all mma reads of smem done

#pragma unroll
    for (int nf = 0; nf < 4; nf++) {
        const int col = wn * 32 + nf * 8 + 2 * (lane & 3);
#pragma unroll
        for (int mf = 0; mf < 4; mf++) {
            const int row = wm * 64 + mf * 16 + (lane >> 2);
            *reinterpret_cast<float2*>(smem + row * EPI_STRIDE + col) =
                make_float2(acc[mf][nf][0], acc[mf][nf][1]);
            *reinterpret_cast<float2*>(smem + (row + 8) * EPI_STRIDE + col) =
                make_float2(acc[mf][nf][2], acc[mf][nf][3]);
        }
    }
    __syncthreads();

    float* out_h = out;
    float* out_c = out + BH;
    float* out_n = out + 2 * BH;
    float* out_m = out + 3 * BH;

    // reader: row (128 floats = 64 h) per 16 lanes; 8 warps x 2 rows x 8.
    const int ln = lane & 15;
    const int rsub = lane >> 4;
    const int hb = ntile * 64 + 4 * ln;           // global h of this 4-vector
    const float4 bf = *reinterpret_cast<const float4*>(bfv + hb);
    const float4 bc = *reinterpret_cast<const float4*>(bcv + hb);

#pragma unroll
    for (int u = 0; u < 8; u++) {
        const int r = wid * 2 + rsub + 16 * u;    // local row
        const float* sp = smem + r * EPI_STRIDE + 8 * ln;
        float4 q0 = *reinterpret_cast<const float4*>(sp);      // pf0 pc0 pf1 pc1
        float4 q1 = *reinterpret_cast<const float4*>(sp + 4);  // pf2 pc2 pf3 pc3

        const size_t g = (size_t)(m0 + r) * H_DIM + hb;
        float4 mp = *reinterpret_cast<const float4*>(mprev + g);
        float4 cp = *reinterpret_cast<const float4*>(cprev + g);
        float4 np = *reinterpret_cast<const float4*>(nprev + g);

        float4 rh, rc, rn, rm;
        cell(q0.x, q0.y, bf.x, bc.x, mp.x, cp.x, np.x, rh.x, rc.x, rn.x, rm.x);
        cell(q0.z, q0.w, bf.y, bc.y, mp.y, cp.y, np.y, rh.y, rc.y, rn.y, rm.y);
        cell(q1.x, q1.y, bf.z, bc.z, mp.z, cp.z, np.z, rh.z, rc.z, rn.z, rm.z);
        cell(q1.z, q1.w, bf.w, bc.w, mp.w, cp.w, np.w, rh.w, rc.w, rn.w, rm.w);

        *reinterpret_cast<float4*>(out_h + g) = rh;
        *reinterpret_cast<float4*>(out_c + g) = rc;
        *reinterpret_cast<float4*>(out_n + g) = rn;
        *reinterpret_cast<float4*>(out_m + g) = rm;
    }
}

// ------------------------------ launcher -----------------------------------
extern "C" void kernel_launch(void* const* d_in, const int* in_sizes, int n_in,
                              void* d_out, int out_size) {
    const float* x     = (const float*)d_in[0];
    const float* hprev = (const float*)d_in[1];
    const float* cprev = (const float*)d_in[2];
    const float* nprev = (const float*)d_in[3];
    const float* mprev = (const float*)d_in[4];
    const float* wf    = (const float*)d_in[5];
    const float* wc    = (const float*)d_in[6];
    const float* rf    = (const float*)d_in[7];
    const float* rc    = (const float*)d_in[8];
    const float* bf    = (const float*)d_in[9];
    const float* bc    = (const float*)d_in[10];

    cudaFuncSetAttribute(smgu_main,
                         cudaFuncAttributeMaxDynamicSharedMemorySize,
                         SMEM_BYTES);

    prep_weights<<<1024, 256>>>(wf, wc, rf, rc);
    prep_act<<<24576, 256>>>((const float4*)x, (const float4*)hprev);
    smgu_main<<<4096, 256, SMEM_BYTES>>>(cprev, nprev, mprev,
                                         bf, bc, (float*)d_out);
}

// round 10
// speedup vs baseline: 2.1575x; 1.0569x over previous
#include <cuda_runtime.h>
#include <cuda_fp16.h>
#include <cstdint>
#include <cstddef>

// ---------------------------------------------------------------------------
// sMGU cell: B=65536, IN=256, H=512
// fp16-input mma.sync GEMM [B,768]@[768,1024] (f/c gates interleaved per
// column pair), fp32 accumulate, fused elementwise epilogue.
// R9: 24 warps/SM. CTA 128x64 (8 warps, warp tile 32x32, acc=32 regs) so
// three 256-thread CTAs co-reside (85-reg budget, no spills). The R6->R8
// occupancy ladder (-46/-41/-116 us) says warp count is the binding resource.
// ---------------------------------------------------------------------------

#define H_DIM   512
#define BH      33554432ull            // B*H
#define KTOT    768
#define KC      32                     // k-chunk (halves)
#define NCHUNK  24                     // 768/32
#define NSTAGE  3
#define ROWH    40                     // smem row stride in halves (pad 32->40)
#define ROWB    (ROWH * 2)             // 80 bytes
#define STG_B   ((128 + 64) * ROWB)    // bytes per stage (A + B tiles) = 15360
#define EPI_STRIDE 68                  // epilogue smem row stride (floats)
#define SMEM_BYTES (NSTAGE * STG_B)    // 46080 >= 128*68*4 (34816)

// fp16 operands (RN-rounded once in prep).
// g_Ah[row][k]: k<256 = x[row], k>=256 = h_prev[row].
// g_Wth[n][k]:  h = n>>1, gate = n&1 (0=f, 1=c).
__device__ __half g_Ah [65536ull * KTOT];
__device__ __half g_Wth[1024 * KTOT];

// ------------------------------- helpers -----------------------------------
__device__ __forceinline__ uint32_t smem_u32(const void* p) {
    uint32_t a;
    asm("{ .reg .u64 t; cvta.to.shared.u64 t, %1; cvt.u32.u64 %0, t; }"
        : "=r"(a) : "l"(p));
    return a;
}
__device__ __forceinline__ void cp16(uint32_t dst, const void* src) {
    asm volatile("cp.async.cg.shared.global [%0], [%1], 16;"
                 :: "r"(dst), "l"(src));
}
__device__ __forceinline__ void ldm_x4(uint32_t* r, uint32_t addr) {
    asm volatile("ldmatrix.sync.aligned.m8n8.x4.shared.b16 {%0,%1,%2,%3}, [%4];"
                 : "=r"(r[0]), "=r"(r[1]), "=r"(r[2]), "=r"(r[3]) : "r"(addr));
}
__device__ __forceinline__ void mma_f16(float* d, const uint32_t* a,
                                        const uint32_t* b) {
    asm volatile(
        "mma.sync.aligned.m16n8k16.row.col.f32.f16.f16.f32 "
        "{%0,%1,%2,%3}, {%4,%5,%6,%7}, {%8,%9}, {%0,%1,%2,%3};"
        : "+f"(d[0]), "+f"(d[1]), "+f"(d[2]), "+f"(d[3])
        : "r"(a[0]), "r"(a[1]), "r"(a[2]), "r"(a[3]), "r"(b[0]), "r"(b[1]));
}

__device__ __forceinline__ float tanh_fast(float v) {
    float e = __expf(2.0f * v);
    return 1.0f - __fdividef(2.0f, e + 1.0f);
}
__device__ __forceinline__ void cell(float df, float dc, float bfe, float bce,
                                     float mpv, float cpv, float npv,
                                     float& h, float& c, float& n, float& m) {
    float a  = df + bfe + mpv;              // log f_t + m_prev
    m = fmaxf(a, 0.0f);
    float e  = __expf(-fabsf(a));           // one exp covers both branches
    float fp = (a >= 0.0f) ? 1.0f : e;      // exp(a - m)
    float ip = (a >= 0.0f) ? e : 1.0f;      // exp(-m)
    float th = tanh_fast(dc + bce);
    c = fp * cpv + ip * th;
    n = fp * npv + ip;
    h = tanh_fast(__fdividef(c, fmaxf(n, 1e-8f)));
}

// ------------------------------ prep kernels -------------------------------
__global__ void prep_weights(const float* __restrict__ wf,
                             const float* __restrict__ wc,
                             const float* __restrict__ rf,
                             const float* __restrict__ rc) {
    int n = blockIdx.x;                 // 0..1023
    int h = n >> 1, gate = n & 1;
    const float* W = gate ? wc : wf;
    const float* R = gate ? rc : rf;
    for (int k = threadIdx.x; k < KTOT; k += blockDim.x) {
        float v = (k < 256) ? W[(size_t)k * H_DIM + h]
                            : R[(size_t)(k - 256) * H_DIM + h];
        g_Wth[(size_t)n * KTOT + k] = __float2half_rn(v);
    }
}

// one thread = 8 halves of g_Ah (16B store)
__global__ void prep_act(const float4* __restrict__ x4,
                         const float4* __restrict__ h4) {
    size_t idx = (size_t)blockIdx.x * blockDim.x + threadIdx.x;
    size_t row = idx / 96;
    int    q   = (int)(idx % 96);       // 8-half group; k0 = q*8
    float4 a, b;
    if (q < 32) {                       // from x
        a = x4[row * 64 + q * 2];
        b = x4[row * 64 + q * 2 + 1];
    } else {                            // from h_prev
        a = h4[row * 128 + (q - 32) * 2];
        b = h4[row * 128 + (q - 32) * 2 + 1];
    }
    __half2 p0 = __float22half2_rn(make_float2(a.x, a.y));
    __half2 p1 = __float22half2_rn(make_float2(a.z, a.w));
    __half2 p2 = __float22half2_rn(make_float2(b.x, b.y));
    __half2 p3 = __float22half2_rn(make_float2(b.z, b.w));
    uint4 v;
    v.x = *reinterpret_cast<uint32_t*>(&p0);
    v.y = *reinterpret_cast<uint32_t*>(&p1);
    v.z = *reinterpret_cast<uint32_t*>(&p2);
    v.w = *reinterpret_cast<uint32_t*>(&p3);
    reinterpret_cast<uint4*>(g_Ah)[idx] = v;
}

// ------------------------------ main kernel --------------------------------
// CTA 128 rows x 64 cols. 8 warps, (wm 0..3) x (wn 0..1), warp tile 32x32.
extern "C" __global__ void __launch_bounds__(256, 3)
smgu_main(const float* __restrict__ cprev, const float* __restrict__ nprev,
          const float* __restrict__ mprev, const float* __restrict__ bfv,
          const float* __restrict__ bcv,   float* __restrict__ out) {
    extern __shared__ float smem[];
    const int tid  = threadIdx.x;
    const int lane = tid & 31, wid = tid >> 5;
    const int wm   = wid & 3,  wn  = wid >> 2;
    const int mtile = (int)blockIdx.x >> 4;
    const int ntile = (int)blockIdx.x & 15;
    const int m0  = mtile * 128;
    const int ncb = ntile * 64;

    const uint32_t sbase = smem_u32(smem);

    // loader mapping: A 128x32h = 512 cp16 (2/thread), B 64x32h = 256 (1/thr)
    const int arow0 = tid >> 2,          aseg0 = tid & 3;          // u=0
    const int arow1 = (tid + 256) >> 2,  aseg1 = tid & 3;          // u=1
    const int brow  = tid >> 2,          bseg  = tid & 3;
    const __half* aptr0 = g_Ah  + (size_t)(m0 + arow0) * KTOT + aseg0 * 8;
    const __half* aptr1 = g_Ah  + (size_t)(m0 + arow1) * KTOT + aseg1 * 8;
    const __half* bptr  = g_Wth + (size_t)(ncb + brow) * KTOT + bseg * 8;
    const uint32_t ad0 = (uint32_t)(arow0 * ROWB + aseg0 * 16);
    const uint32_t ad1 = (uint32_t)(arow1 * ROWB + aseg1 * 16);
    const uint32_t bd  = (uint32_t)(128 * ROWB + brow * ROWB + bseg * 16);

    float acc[2][4][4];                  // mf x nf x frag = 32 regs
#pragma unroll
    for (int i = 0; i < 2; i++)
#pragma unroll
        for (int j = 0; j < 4; j++)
#pragma unroll
            for (int r = 0; r < 4; r++) acc[i][j][r] = 0.0f;

    auto load = [&](int s) {
        const uint32_t sb = sbase + (uint32_t)(s * STG_B);
        cp16(sb + ad0, aptr0);
        cp16(sb + ad1, aptr1);
        cp16(sb + bd,  bptr);
        asm volatile("cp.async.commit_group;" ::: "memory");
        aptr0 += KC; aptr1 += KC; bptr += KC;
    };

    load(0);
    load(1);

    // ldmatrix per-thread base offsets (bytes, within a stage)
    const uint32_t a_off = (uint32_t)((wm * 32 + (lane & 15)) * ROWB
                                      + (lane >> 4) * 16);
    const uint32_t b_off = (uint32_t)(128 * ROWB
                                      + (wn * 32 + ((lane >> 4) << 3)
                                         + (lane & 7)) * ROWB
                                      + ((lane >> 3) & 1) * 16);

    for (int c = 0; c < NCHUNK; c++) {
        const int s = c % NSTAGE;
        asm volatile("cp.async.wait_group 1;" ::: "memory");
        __syncthreads();   // all warps have chunk c; all done reading c-1

        if (c + 2 < NCHUNK) load((c + 2) % NSTAGE);     // stage of c-1
        else asm volatile("cp.async.commit_group;" ::: "memory");

        const uint32_t stg = sbase + (uint32_t)(s * STG_B);
        const uint32_t ab  = stg + a_off;
        const uint32_t bb  = stg + b_off;
#pragma unroll
        for (int kk = 0; kk < 2; kk++) {             // two k16 steps
            const uint32_t kb = (uint32_t)(kk * 32); // 16 halves
            uint32_t afr[2][4];
#pragma unroll
            for (int mf = 0; mf < 2; mf++)
                ldm_x4(afr[mf], ab + (uint32_t)(mf * 16 * ROWB) + kb);
#pragma unroll
            for (int p = 0; p < 2; p++) {            // stream B pairs
                uint32_t br[4];
                ldm_x4(br, bb + (uint32_t)(p * 16 * ROWB) + kb);
#pragma unroll
                for (int mf = 0; mf < 2; mf++) {
                    mma_f16(acc[mf][2 * p],     afr[mf], br);
                    mma_f16(acc[mf][2 * p + 1], afr[mf], br + 2);
                }
            }
        }
    }

    // ------------------- epilogue: stage through SMEM ---------------------
    __syncthreads();                    // all mma reads of smem done

#pragma unroll
    for (int nf = 0; nf < 4; nf++) {
        const int col = wn * 32 + nf * 8 + 2 * (lane & 3);
#pragma unroll
        for (int mf = 0; mf < 2; mf++) {
            const int row = wm * 32 + mf * 16 + (lane >> 2);
            *reinterpret_cast<float2*>(smem + row * EPI_STRIDE + col) =
                make_float2(acc[mf][nf][0], acc[mf][nf][1]);
            *reinterpret_cast<float2*>(smem + (row + 8) * EPI_STRIDE + col) =
                make_float2(acc[mf][nf][2], acc[mf][nf][3]);
        }
    }
    __syncthreads();

    float* out_h = out;
    float* out_c = out + BH;
    float* out_n = out + 2 * BH;
    float* out_m = out + 3 * BH;

    // reader: row (64 floats = 32 h) per 8 lanes; warp does 4 rows/iter;
    // 8 warps x 4 rows x 4 iters = 128 rows.
    const int ln = lane & 7;
    const int rsub = lane >> 3;                   // 0..3
    const int hb = ntile * 32 + 4 * ln;           // global h of this 4-vector
    const float4 bf = *reinterpret_cast<const float4*>(bfv + hb);
    const float4 bc = *reinterpret_cast<const float4*>(bcv + hb);

#pragma unroll
    for (int u = 0; u < 4; u++) {
        const int r = wid * 4 + rsub + 32 * u;    // local row
        const float* sp = smem + r * EPI_STRIDE + 8 * ln;
        float4 q0 = *reinterpret_cast<const float4*>(sp);      // pf0 pc0 pf1 pc1
        float4 q1 = *reinterpret_cast<const float4*>(sp + 4);  // pf2 pc2 pf3 pc3

        const size_t g = (size_t)(m0 + r) * H_DIM + hb;
        float4 mp = *reinterpret_cast<const float4*>(mprev + g);
        float4 cp = *reinterpret_cast<const float4*>(cprev + g);
        float4 np = *reinterpret_cast<const float4*>(nprev + g);

        float4 rh, rc, rn, rm;
        cell(q0.x, q0.y, bf.x, bc.x, mp.x, cp.x, np.x, rh.x, rc.x, rn.x, rm.x);
        cell(q0.z, q0.w, bf.y, bc.y, mp.y, cp.y, np.y, rh.y, rc.y, rn.y, rm.y);
        cell(q1.x, q1.y, bf.z, bc.z, mp.z, cp.z, np.z, rh.z, rc.z, rn.z, rm.z);
        cell(q1.z, q1.w, bf.w, bc.w, mp.w, cp.w, np.w, rh.w, rc.w, rn.w, rm.w);

        *reinterpret_cast<float4*>(out_h + g) = rh;
        *reinterpret_cast<float4*>(out_c + g) = rc;
        *reinterpret_cast<float4*>(out_n + g) = rn;
        *reinterpret_cast<float4*>(out_m + g) = rm;
    }
}

// ------------------------------ launcher -----------------------------------
extern "C" void kernel_launch(void* const* d_in, const int* in_sizes, int n_in,
                              void* d_out, int out_size) {
    const float* x     = (const float*)d_in[0];
    const float* hprev = (const float*)d_in[1];
    const float* cprev = (const float*)d_in[2];
    const float* nprev = (const float*)d_in[3];
    const float* mprev = (const float*)d_in[4];
    const float* wf    = (const float*)d_in[5];
    const float* wc    = (const float*)d_in[6];
    const float* rf    = (const float*)d_in[7];
    const float* rc    = (const float*)d_in[8];
    const float* bf    = (const float*)d_in[9];
    const float* bc    = (const float*)d_in[10];

    cudaFuncSetAttribute(smgu_main,
                         cudaFuncAttributeMaxDynamicSharedMemorySize,
                         SMEM_BYTES);

    prep_weights<<<1024, 256>>>(wf, wc, rf, rc);
    prep_act<<<24576, 256>>>((const float4*)x, (const float4*)hprev);
    smgu_main<<<8192, 256, SMEM_BYTES>>>(cprev, nprev, mprev,
                                         bf, bc, (float*)d_out);
}